// round 17
// baseline (speedup 1.0000x reference)
#include <cuda_runtime.h>
#include <cstdint>

// DispCorr via mma.sync tf32 m16n8k8 (base sm_103), round 17:
// r14 compute shape + cp.async staging + 2-tile double-buffer per CTA.
//
// CTA = (b, h, q-pair p): tiles q=2p, 2p+1, each w in [w0, w0+128), all d<64.
// Per tile buffer (11520 floats, stride 36):
//   rows   0..127: A[m][k] = L[k][w0+m]          (raw fp32; tf32 cvt at frag load)
//   rows 128..319: B[n][k] = R[k][w0-64+n]       (s<0 rows zeroed via STS)
// Both tiles' cp.asyncs issued up-front (groups 0,1) -> DRAM busy while computing.
// P[m,n] = sum_k A B ; out[d, w0+m] = P[m, m+64-d], band jl in [0,80).
// Warp w: m0=16w, 10 n-tiles x 4 ks = 40 HMMA, acc regs.
// Epilogue: scatter -> ob[64][132] (aliases buf0 after its reads complete) -> float4 STG.

#define ROWS  320
#define RSTR  36
#define BUF_FLOATS (ROWS * RSTR)             // 11520
#define OB_STRIDE 132
#define SMEM_BYTES (2 * BUF_FLOATS * 4)      // 92160
#define CSTR ((size_t)131072)                // 256*512 channel stride

static __device__ __forceinline__ unsigned f2tf32(float f) {
    unsigned u;
    asm("cvt.rna.tf32.f32 %0, %1;" : "=r"(u) : "f"(f));
    return u;
}

static __device__ __forceinline__ uint32_t smem_u32(const void* p) {
    uint32_t a;
    asm("{ .reg .u64 t; cvta.to.shared.u64 t, %1; cvt.u32.u64 %0, t; }"
        : "=r"(a) : "l"(p));
    return a;
}

static __device__ __forceinline__ void cp4(uint32_t dst, const float* src) {
    asm volatile("cp.async.ca.shared.global [%0], [%1], 4;"
                 :: "r"(dst), "l"(src) : "memory");
}

static __device__ __forceinline__ void mma16n8k8(float* c, const unsigned* a,
                                                 const unsigned* b) {
    asm volatile(
        "mma.sync.aligned.m16n8k8.row.col.f32.tf32.tf32.f32 "
        "{%0,%1,%2,%3}, {%4,%5,%6,%7}, {%8,%9}, {%0,%1,%2,%3};"
        : "+f"(c[0]), "+f"(c[1]), "+f"(c[2]), "+f"(c[3])
        : "r"(a[0]), "r"(a[1]), "r"(a[2]), "r"(a[3]), "r"(b[0]), "r"(b[1]));
}

__global__ __launch_bounds__(256, 2)
void disp_corr_mma(const float* __restrict__ x, float* __restrict__ out) {
    extern __shared__ float smem_f[];
    const uint32_t sb = smem_u32(smem_f);

    const int tid  = threadIdx.x;
    const int warp = tid >> 5;       // 0..7
    const int lane = tid & 31;
    const int gid  = lane >> 2;
    const int t    = lane & 3;
    const int bx   = blockIdx.x;     // 0..2047
    const int p    = bx & 1;         // q-pair
    const int bh   = bx >> 1;
    const int b    = bh >> 8;
    const int h    = bh & 255;

    const float* xL = x + (((size_t)b * 64) * 256 + h) * 512;
    const float* xR = xL + 32 * CSTR;

    // ---- Issue async staging for BOTH tiles (groups 0 and 1) ----
#pragma unroll
    for (int tt = 0; tt < 2; ++tt) {
        const int w0 = (2 * p + tt) << 7;
        const uint32_t base = sb + tt * (BUF_FLOATS * 4);
        for (int it = tid; it < ROWS; it += 256) {
            const uint32_t row = base + it * (RSTR * 4);
            if (it < 128) {
                const float* g = xL + w0 + it;
#pragma unroll
                for (int c = 0; c < 32; ++c) cp4(row + c * 4, g + c * CSTR);
            } else {
                const int s = w0 - 192 + it;     // w0 - 64 + (it - 128)
                if (s >= 0) {
                    const float* g = xR + s;
#pragma unroll
                    for (int c = 0; c < 32; ++c) cp4(row + c * 4, g + c * CSTR);
                } else {
                    float* r = smem_f + tt * BUF_FLOATS + it * RSTR;
#pragma unroll
                    for (int qq = 0; qq < 8; ++qq)
                        *(float4*)(r + 4 * qq) = make_float4(0.f, 0.f, 0.f, 0.f);
                }
            }
        }
        asm volatile("cp.async.commit_group;" ::: "memory");
    }

    float* ob = smem_f;              // aliases buf0 (dead by the time it's written)
    const float inv_c = 1.0f / 32.0f;
    const int m0 = 16 * warp;

#pragma unroll
    for (int tt = 0; tt < 2; ++tt) {
        if (tt == 0) asm volatile("cp.async.wait_group 1;" ::: "memory");
        else         asm volatile("cp.async.wait_group 0;" ::: "memory");
        __syncthreads();             // buffer tt ready for all threads

        const float* buf  = smem_f + tt * BUF_FLOATS;
        const float* abuf = buf + (m0 + gid) * RSTR + t;
        const float* bbuf = buf + (128 + m0 + gid) * RSTR + t;

        float acc[10][4];
#pragma unroll
        for (int nt = 0; nt < 10; ++nt)
#pragma unroll
            for (int e = 0; e < 4; ++e) acc[nt][e] = 0.f;

#pragma unroll
        for (int ks = 0; ks < 4; ++ks) {
            unsigned a[4];
            a[0] = f2tf32(abuf[8 * ks]);
            a[1] = f2tf32(abuf[288 + 8 * ks]);       // +8 rows
            a[2] = f2tf32(abuf[8 * ks + 4]);
            a[3] = f2tf32(abuf[288 + 8 * ks + 4]);
#pragma unroll
            for (int nt = 0; nt < 10; ++nt) {
                unsigned bb[2];
                bb[0] = f2tf32(bbuf[nt * 288 + 8 * ks]);
                bb[1] = f2tf32(bbuf[nt * 288 + 8 * ks + 4]);
                mma16n8k8(acc[nt], a, bb);
            }
        }
        __syncthreads();             // all operand reads done (needed for tt=0: ob aliases buf0)

        // ---- Scatter: ob[d][m0+i], d = i - jl + 64 ----
#pragma unroll
        for (int nt = 0; nt < 10; ++nt) {
#pragma unroll
            for (int reg = 0; reg < 4; ++reg) {
                const int i  = gid + 8 * (reg >> 1);
                const int jl = 8 * nt + 2 * t + (reg & 1);
                const int d  = i - jl + 64;
                if ((unsigned)d < 64u)
                    ob[d * OB_STRIDE + m0 + i] = acc[nt][reg];
            }
        }
        __syncthreads();

        // ---- Coalesced store: 64 d-rows x 128 w (float4) ----
        const int w0 = (2 * p + tt) << 7;
        for (int it = tid; it < 2048; it += 256) {
            const int d = it >> 5, f4 = it & 31;
            float4 v = *(float4*)(ob + d * OB_STRIDE + 4 * f4);
            v.x *= inv_c; v.y *= inv_c; v.z *= inv_c; v.w *= inv_c;
            *(float4*)(out + (((size_t)b * 64 + d) * 256 + h) * 512 + w0 + 4 * f4) = v;
        }
    }
}

extern "C" void kernel_launch(void* const* d_in, const int* in_sizes, int n_in,
                              void* d_out, int out_size) {
    const float* x = (const float*)d_in[0];
    float* out = (float*)d_out;
    (void)in_sizes; (void)n_in; (void)out_size;

    cudaFuncSetAttribute(disp_corr_mma,
                         cudaFuncAttributeMaxDynamicSharedMemorySize, SMEM_BYTES);
    disp_corr_mma<<<2048, 256, SMEM_BYTES>>>(x, out);
}